// round 7
// baseline (speedup 1.0000x reference)
#include <cuda_runtime.h>
#include <cstdint>

// NonLocalBlock: B=8, C=512, H=W=64 -> N=4096, CR=128
//   proj  = w_in[384,512] @ x[b,512,4096]   (tf32 TC, cp.async) -> Q,K,G
//   attn  = flash softmax(Q K^T) G          (tf32 TC, cp.async) -> Y
//   out   = x + w_out[512,128] @ Y^T        (tf32 TC)           -> out

#define BATCH 8
#define CIN   512
#define NTOK  4096
#define CRD   128

__device__ float g_q[(size_t)BATCH * NTOK * CRD];
__device__ float g_k[(size_t)BATCH * NTOK * CRD];
__device__ float g_g[(size_t)BATCH * NTOK * CRD];
__device__ float g_y[(size_t)BATCH * NTOK * CRD];

#define CP_ASYNC16(dst_u32, src_ptr) \
    asm volatile("cp.async.cg.shared.global [%0], [%1], 16;\n" \
                 :: "r"(dst_u32), "l"(src_ptr))
#define CP_COMMIT()  asm volatile("cp.async.commit_group;\n" ::: "memory")
#define CP_WAIT0()   asm volatile("cp.async.wait_group 0;\n" ::: "memory")

__device__ __forceinline__ uint32_t smem_u32(const void* p) {
    return (uint32_t)__cvta_generic_to_shared(p);
}

// ---------------------------------------------------------------------------
// tf32 mma.sync m16n8k8 (validated R3/R5 fragment layout).
// ---------------------------------------------------------------------------
__device__ __forceinline__ void mma_tf32(float d[4], const uint32_t a[4],
                                         uint32_t b0, uint32_t b1,
                                         const float c[4]) {
    asm volatile(
        "mma.sync.aligned.m16n8k8.row.col.f32.tf32.tf32.f32 "
        "{%0,%1,%2,%3}, {%4,%5,%6,%7}, {%8,%9}, {%10,%11,%12,%13};\n"
        : "=f"(d[0]), "=f"(d[1]), "=f"(d[2]), "=f"(d[3])
        : "r"(a[0]), "r"(a[1]), "r"(a[2]), "r"(a[3]),
          "r"(b0), "r"(b1),
          "f"(c[0]), "f"(c[1]), "f"(c[2]), "f"(c[3]));
}

// ---------------------------------------------------------------------------
// Kernel 1: projection GEMM, tf32 TC, cp.async double-buffered K-chunks.
// CTA 128 tok x 128 feat, K=512 in 16 chunks of 32.  grid (32, 3, 8).
// dyn smem: 2*Xs[32][136] + 2*Ws[128][36] = 71,680 B.
// ---------------------------------------------------------------------------
#define XS_S 136
#define WJ_S 36
#define XS_TILE (32 * XS_S)
#define WJ_TILE (128 * WJ_S)
#define PROJ_SMEM ((2 * XS_TILE + 2 * WJ_TILE) * 4)

__device__ __forceinline__ void proj_load_chunk(float* Xd, float* Wd,
                                                const float* xb, const float* wb,
                                                int c0, int tid) {
#pragma unroll
    for (int i = 0; i < 4; i++) {
        int idx = i * 256 + tid;                 // 0..1023
        int r = idx >> 5, c4 = (idx & 31) << 2;  // Xs: 32 rows x 128 cols
        CP_ASYNC16(smem_u32(Xd + r * XS_S + c4),
                   xb + (size_t)(c0 + r) * NTOK + c4);
        int j = idx >> 3, f4 = (idx & 7) << 2;   // Ws: 128 rows x 32 cols
        CP_ASYNC16(smem_u32(Wd + j * WJ_S + f4),
                   wb + (size_t)j * CIN + c0 + f4);
    }
}

__global__ __launch_bounds__(256) void proj_tc_kernel(const float* __restrict__ x,
                                                      const float* __restrict__ w_in) {
    extern __shared__ float psm[];
    float* XsB[2] = {psm, psm + XS_TILE};
    float* WsB[2] = {psm + 2 * XS_TILE, psm + 2 * XS_TILE + WJ_TILE};

    const int n0 = blockIdx.x * 128;
    const int j0 = blockIdx.y * 128;
    const int b  = blockIdx.z;
    const int tid  = threadIdx.x;
    const int w    = tid >> 5;
    const int lane = tid & 31;
    const int gp = lane >> 2, tg = lane & 3;
    const int wm = w & 3;
    const int wn = w >> 2;

    const float* xb = x + (size_t)b * CIN * NTOK + n0;
    const float* wb = w_in + (size_t)j0 * CIN;

    float acc[2][8][4];
#pragma unroll
    for (int mt = 0; mt < 2; mt++)
#pragma unroll
        for (int nt = 0; nt < 8; nt++)
#pragma unroll
            for (int e = 0; e < 4; e++) acc[mt][nt][e] = 0.f;

    proj_load_chunk(XsB[0], WsB[0], xb, wb, 0, tid);
    CP_COMMIT();

    for (int ch = 0; ch < 16; ch++) {
        CP_WAIT0();
        __syncthreads();
        if (ch + 1 < 16) {
            proj_load_chunk(XsB[(ch + 1) & 1], WsB[(ch + 1) & 1],
                            xb, wb, (ch + 1) * 32, tid);
            CP_COMMIT();
        }
        const float* Xs = XsB[ch & 1];
        const float* Ws = WsB[ch & 1];

#pragma unroll
        for (int kk = 0; kk < 4; kk++) {
            uint32_t a[2][4];
#pragma unroll
            for (int mt = 0; mt < 2; mt++) {
                int m = wm * 32 + mt * 16;
                a[mt][0] = __float_as_uint(Xs[(kk * 8 + tg) * XS_S + m + gp]);
                a[mt][1] = __float_as_uint(Xs[(kk * 8 + tg) * XS_S + m + gp + 8]);
                a[mt][2] = __float_as_uint(Xs[(kk * 8 + tg + 4) * XS_S + m + gp]);
                a[mt][3] = __float_as_uint(Xs[(kk * 8 + tg + 4) * XS_S + m + gp + 8]);
            }
#pragma unroll
            for (int nt = 0; nt < 8; nt++) {
                int j = wn * 64 + nt * 8;
                uint32_t b0 = __float_as_uint(Ws[(j + gp) * WJ_S + kk * 8 + tg]);
                uint32_t b1 = __float_as_uint(Ws[(j + gp) * WJ_S + kk * 8 + tg + 4]);
                mma_tf32(acc[0][nt], a[0], b0, b1, acc[0][nt]);
                mma_tf32(acc[1][nt], a[1], b0, b1, acc[1][nt]);
            }
        }
    }

    float* dst = (j0 == 0) ? g_q : (j0 == 128) ? g_k : g_g;
    float* base = dst + ((size_t)b * NTOK + n0 + wm * 32) * CRD + wn * 64;
#pragma unroll
    for (int mt = 0; mt < 2; mt++)
#pragma unroll
        for (int nt = 0; nt < 8; nt++) {
            *(float2*)&base[(mt * 16 + gp) * CRD + nt * 8 + 2 * tg] =
                make_float2(acc[mt][nt][0], acc[mt][nt][1]);
            *(float2*)&base[(mt * 16 + gp + 8) * CRD + nt * 8 + 2 * tg] =
                make_float2(acc[mt][nt][2], acc[mt][nt][3]);
        }
}

// ---------------------------------------------------------------------------
// Kernel 2: flash attention, tf32 TC, cp.async double-buffered K/G tiles.
// CTA = 128 q-rows, kv tiles of 64, grid (32, 8), 256 thr.
// dyn smem: 2*Ks[64][132] + 2*Gs[64][136] + Ps[8][16][68] = 172,032 B.
// ---------------------------------------------------------------------------
#define KS_STRIDE 132
#define GS_STRIDE 136
#define PS_STRIDE 68
#define KS_TILE (64 * KS_STRIDE)
#define GS_TILE (64 * GS_STRIDE)
#define ATTN_SMEM ((2 * KS_TILE + 2 * GS_TILE + 8 * 16 * PS_STRIDE) * 4)

__device__ __forceinline__ void attn_load_tile(float* Kd, float* Gd,
                                               const float* Kt, const float* Gt,
                                               int tid) {
#pragma unroll
    for (int i = 0; i < 8; i++) {
        int idx = i * 256 + tid;                 // 0..2047
        int r = idx >> 5, c4 = (idx & 31) << 2;
        CP_ASYNC16(smem_u32(Kd + r * KS_STRIDE + c4), Kt + r * CRD + c4);
        CP_ASYNC16(smem_u32(Gd + r * GS_STRIDE + c4), Gt + r * CRD + c4);
    }
}

__global__ __launch_bounds__(256, 1) void attn_tc_kernel() {
    extern __shared__ float smf[];
    float* KsB[2] = {smf, smf + KS_TILE};
    float* GsB[2] = {smf + 2 * KS_TILE, smf + 2 * KS_TILE + GS_TILE};
    float* Ps = smf + 2 * KS_TILE + 2 * GS_TILE;

    const int q0  = blockIdx.x * 128;
    const int b   = blockIdx.y;
    const int tid = threadIdx.x;
    const int w    = tid >> 5;
    const int lane = tid & 31;
    const int gp = lane >> 2;
    const int tg = lane & 3;

    const float* Kg = g_k + (size_t)b * NTOK * CRD;
    const float* Gg = g_g + (size_t)b * NTOK * CRD;

    // Prologue: start tile 0 streaming while we fetch Q fragments.
    attn_load_tile(KsB[0], GsB[0], Kg, Gg, tid);
    CP_COMMIT();

    const float* Qg = g_q + ((size_t)b * NTOK + q0 + w * 16) * CRD;
    uint32_t qf[16][4];
#pragma unroll
    for (int t = 0; t < 16; t++) {
        qf[t][0] = __float_as_uint(Qg[gp * CRD + t * 8 + tg]);
        qf[t][1] = __float_as_uint(Qg[(gp + 8) * CRD + t * 8 + tg]);
        qf[t][2] = __float_as_uint(Qg[gp * CRD + t * 8 + tg + 4]);
        qf[t][3] = __float_as_uint(Qg[(gp + 8) * CRD + t * 8 + tg + 4]);
    }

    float o[16][4];
#pragma unroll
    for (int j = 0; j < 16; j++)
#pragma unroll
        for (int e = 0; e < 4; e++) o[j][e] = 0.f;
    float m0 = -3.0e38f, m1 = -3.0e38f, l0 = 0.f, l1 = 0.f;

    float* Pw = Ps + w * 16 * PS_STRIDE;

    for (int kt = 0; kt < NTOK / 64; kt++) {
        CP_WAIT0();          // tile kt landed
        __syncthreads();     // visible to all warps; prev iter compute done
        if (kt + 1 < NTOK / 64) {
            attn_load_tile(KsB[(kt + 1) & 1], GsB[(kt + 1) & 1],
                           Kg + (size_t)(kt + 1) * 64 * CRD,
                           Gg + (size_t)(kt + 1) * 64 * CRD, tid);
            CP_COMMIT();
        }
        const float* Ks = KsB[kt & 1];
        const float* Gs = GsB[kt & 1];

        // GEMM1: S[16q x 64kv] = Q x K^T
        float s[8][4];
#pragma unroll
        for (int j = 0; j < 8; j++)
#pragma unroll
            for (int e = 0; e < 4; e++) s[j][e] = 0.f;
#pragma unroll
        for (int t = 0; t < 16; t++) {
#pragma unroll
            for (int j = 0; j < 8; j++) {
                uint32_t b0 = __float_as_uint(
                    Ks[(j * 8 + gp) * KS_STRIDE + t * 8 + tg]);
                uint32_t b1 = __float_as_uint(
                    Ks[(j * 8 + gp) * KS_STRIDE + t * 8 + tg + 4]);
                mma_tf32(s[j], qf[t], b0, b1, s[j]);
            }
        }

        // Online softmax (rows gp / gp+8, each across a 4-lane quad).
        float mx0 = -3.0e38f, mx1 = -3.0e38f;
#pragma unroll
        for (int j = 0; j < 8; j++) {
            mx0 = fmaxf(mx0, fmaxf(s[j][0], s[j][1]));
            mx1 = fmaxf(mx1, fmaxf(s[j][2], s[j][3]));
        }
        mx0 = fmaxf(mx0, __shfl_xor_sync(0xffffffffu, mx0, 1));
        mx0 = fmaxf(mx0, __shfl_xor_sync(0xffffffffu, mx0, 2));
        mx1 = fmaxf(mx1, __shfl_xor_sync(0xffffffffu, mx1, 1));
        mx1 = fmaxf(mx1, __shfl_xor_sync(0xffffffffu, mx1, 2));
        float nm0 = fmaxf(m0, mx0), nm1 = fmaxf(m1, mx1);
        float corr0 = __expf(m0 - nm0), corr1 = __expf(m1 - nm1);
        m0 = nm0; m1 = nm1;
        float ps0 = 0.f, ps1 = 0.f;
#pragma unroll
        for (int j = 0; j < 8; j++) {
            s[j][0] = __expf(s[j][0] - nm0);
            s[j][1] = __expf(s[j][1] - nm0);
            s[j][2] = __expf(s[j][2] - nm1);
            s[j][3] = __expf(s[j][3] - nm1);
            ps0 += s[j][0] + s[j][1];
            ps1 += s[j][2] + s[j][3];
        }
        ps0 += __shfl_xor_sync(0xffffffffu, ps0, 1);
        ps0 += __shfl_xor_sync(0xffffffffu, ps0, 2);
        ps1 += __shfl_xor_sync(0xffffffffu, ps1, 1);
        ps1 += __shfl_xor_sync(0xffffffffu, ps1, 2);
        l0 = l0 * corr0 + ps0;
        l1 = l1 * corr1 + ps1;
#pragma unroll
        for (int j = 0; j < 16; j++) {
            o[j][0] *= corr0; o[j][1] *= corr0;
            o[j][2] *= corr1; o[j][3] *= corr1;
        }

        // P -> warp-private smem (C-frag -> row-major).
#pragma unroll
        for (int j = 0; j < 8; j++) {
            *(float2*)&Pw[gp * PS_STRIDE + j * 8 + 2 * tg] =
                make_float2(s[j][0], s[j][1]);
            *(float2*)&Pw[(gp + 8) * PS_STRIDE + j * 8 + 2 * tg] =
                make_float2(s[j][2], s[j][3]);
        }
        __syncwarp();

        // GEMM2: O[16q x 128c] += P x G
#pragma unroll
        for (int ss = 0; ss < 8; ss++) {
            uint32_t a[4];
            a[0] = __float_as_uint(Pw[gp * PS_STRIDE + ss * 8 + tg]);
            a[1] = __float_as_uint(Pw[(gp + 8) * PS_STRIDE + ss * 8 + tg]);
            a[2] = __float_as_uint(Pw[gp * PS_STRIDE + ss * 8 + tg + 4]);
            a[3] = __float_as_uint(Pw[(gp + 8) * PS_STRIDE + ss * 8 + tg + 4]);
#pragma unroll
            for (int j2 = 0; j2 < 16; j2++) {
                uint32_t b0 = __float_as_uint(
                    Gs[(ss * 8 + tg) * GS_STRIDE + j2 * 8 + gp]);
                uint32_t b1 = __float_as_uint(
                    Gs[(ss * 8 + tg + 4) * GS_STRIDE + j2 * 8 + gp]);
                mma_tf32(o[j2], a, b0, b1, o[j2]);
            }
        }
        __syncwarp();   // P reads done before next iteration overwrites
    }

    const float inv0 = 1.f / l0, inv1 = 1.f / l1;
    float* Yg = g_y + ((size_t)b * NTOK + q0 + w * 16) * CRD;
#pragma unroll
    for (int j2 = 0; j2 < 16; j2++) {
        *(float2*)&Yg[gp * CRD + j2 * 8 + 2 * tg] =
            make_float2(o[j2][0] * inv0, o[j2][1] * inv0);
        *(float2*)&Yg[(gp + 8) * CRD + j2 * 8 + 2 * tg] =
            make_float2(o[j2][2] * inv1, o[j2][3] * inv1);
    }
}

// ---------------------------------------------------------------------------
// Kernel 3: output GEMM + residual (unchanged, validated R5).
// ---------------------------------------------------------------------------
#define OA_S 36

__global__ __launch_bounds__(256) void out_tc_kernel(const float* __restrict__ x,
                                                     const float* __restrict__ w_out,
                                                     float* __restrict__ out) {
    __shared__ float As[128 * OA_S];
    __shared__ float Bs[128 * OA_S];
    const int n0 = blockIdx.x * 128;
    const int c0 = blockIdx.y * 128;
    const int b  = blockIdx.z;
    const int tid  = threadIdx.x;
    const int w    = tid >> 5;
    const int lane = tid & 31;
    const int gp = lane >> 2, tg = lane & 3;
    const int wm = w & 3;
    const int wn = w >> 2;

    const float* Wg = w_out + (size_t)c0 * CRD;
    const float* Yg = g_y + ((size_t)b * NTOK + n0) * CRD;

    float acc[2][8][4];
#pragma unroll
    for (int mt = 0; mt < 2; mt++)
#pragma unroll
        for (int nt = 0; nt < 8; nt++)
#pragma unroll
            for (int e = 0; e < 4; e++) acc[mt][nt][e] = 0.f;

    for (int k0 = 0; k0 < CRD; k0 += 32) {
        __syncthreads();
#pragma unroll
        for (int i = 0; i < 4; i++) {
            int idx = i * 256 + tid;
            int r = idx >> 3, f4 = (idx & 7) << 2;
            *(float4*)&As[r * OA_S + f4] =
                *(const float4*)(Wg + (size_t)r * CRD + k0 + f4);
            *(float4*)&Bs[r * OA_S + f4] =
                *(const float4*)(Yg + (size_t)r * CRD + k0 + f4);
        }
        __syncthreads();

#pragma unroll
        for (int kk = 0; kk < 4; kk++) {
            uint32_t a[2][4];
#pragma unroll
            for (int mt = 0; mt < 2; mt++) {
                int c = wm * 32 + mt * 16;
                a[mt][0] = __float_as_uint(As[(c + gp) * OA_S + kk * 8 + tg]);
                a[mt][1] = __float_as_uint(As[(c + gp + 8) * OA_S + kk * 8 + tg]);
                a[mt][2] = __float_as_uint(As[(c + gp) * OA_S + kk * 8 + tg + 4]);
                a[mt][3] = __float_as_uint(As[(c + gp + 8) * OA_S + kk * 8 + tg + 4]);
            }
#pragma unroll
            for (int nt = 0; nt < 8; nt++) {
                int n = wn * 64 + nt * 8;
                uint32_t b0 = __float_as_uint(Bs[(n + gp) * OA_S + kk * 8 + tg]);
                uint32_t b1 = __float_as_uint(Bs[(n + gp) * OA_S + kk * 8 + tg + 4]);
                mma_tf32(acc[0][nt], a[0], b0, b1, acc[0][nt]);
                mma_tf32(acc[1][nt], a[1], b0, b1, acc[1][nt]);
            }
        }
    }

#pragma unroll
    for (int mt = 0; mt < 2; mt++)
#pragma unroll
        for (int nt = 0; nt < 8; nt++) {
            size_t r0 = ((size_t)b * CIN + c0 + wm * 32 + mt * 16 + gp) * NTOK
                        + n0 + wn * 64 + nt * 8 + 2 * tg;
            size_t r1 = r0 + (size_t)8 * NTOK;
            float2 x0 = *(const float2*)(x + r0);
            float2 x1 = *(const float2*)(x + r1);
            *(float2*)(out + r0) = make_float2(x0.x + acc[mt][nt][0],
                                               x0.y + acc[mt][nt][1]);
            *(float2*)(out + r1) = make_float2(x1.x + acc[mt][nt][2],
                                               x1.y + acc[mt][nt][3]);
        }
}

// ---------------------------------------------------------------------------
extern "C" void kernel_launch(void* const* d_in, const int* in_sizes, int n_in,
                              void* d_out, int out_size) {
    const float* x = nullptr; const float* w_in = nullptr; const float* w_out = nullptr;
    for (int i = 0; i < n_in; i++) {
        if (in_sizes[i] == BATCH * CIN * NTOK)      x     = (const float*)d_in[i];
        else if (in_sizes[i] == 3 * CRD * CIN)      w_in  = (const float*)d_in[i];
        else if (in_sizes[i] == CIN * CRD)          w_out = (const float*)d_in[i];
    }

    static int attr_done = 0;
    if (!attr_done) {
        cudaFuncSetAttribute(attn_tc_kernel,
                             cudaFuncAttributeMaxDynamicSharedMemorySize, ATTN_SMEM);
        cudaFuncSetAttribute(attn_tc_kernel,
                             cudaFuncAttributePreferredSharedMemoryCarveout, 100);
        cudaFuncSetAttribute(proj_tc_kernel,
                             cudaFuncAttributeMaxDynamicSharedMemorySize, PROJ_SMEM);
        attr_done = 1;
    }

    proj_tc_kernel<<<dim3(32, 3, 8), 256, PROJ_SMEM>>>(x, w_in);
    attn_tc_kernel<<<dim3(32, 8), 256, ATTN_SMEM>>>();
    out_tc_kernel<<<dim3(32, 4, 8), 256>>>(x, w_out, (float*)d_out);
}